// round 4
// baseline (speedup 1.0000x reference)
#include <cuda_runtime.h>
#include <cuda_bf16.h>
#include <math.h>

#define MTOT 8192
#define BGR  16
#define NATOM 512
#define FDIM 128
#define HID  64
#define DDIM 16
#define SEIN 95
#define EHIN 159
#define APB  8          // atoms per block in pair kernel
#define NBLK (MTOT/APB) // 1024

__device__ float g_src[MTOT*DDIM];
__device__ float g_mean[BGR*DDIM];
__device__ float g_shell[MTOT*SEIN];

__device__ __forceinline__ float siluf(float x){ return x * (1.f/(1.f + __expf(-x))); }

// block reduction: returns total sum to all threads. red must hold >= nwarps floats.
__device__ __forceinline__ float blockSum(float v, float* red, int nw){
  #pragma unroll
  for (int o=16;o>0;o>>=1) v += __shfl_xor_sync(0xffffffffu, v, o);
  if ((threadIdx.x&31)==0) red[threadIdx.x>>5]=v;
  __syncthreads();
  float s=0.f;
  for(int k=0;k<nw;k++) s += red[k];
  __syncthreads();
  return s;
}

// ---------------- kernel 1: per-atom source features ----------------
__global__ void src_kernel(const float* __restrict__ x,
                           const float* __restrict__ lg, const float* __restrict__ lb,
                           const float* __restrict__ w1, const float* __restrict__ b1,
                           const float* __restrict__ w2, const float* __restrict__ b2,
                           const float* __restrict__ sg, const float* __restrict__ sb)
{
  __shared__ float sh[FDIM];
  __shared__ float red[4];
  __shared__ float hidsh[HID];
  __shared__ float pre[DDIM];
  int atom=blockIdx.x, t=threadIdx.x;
  float v = x[atom*FDIM+t];
  float m = blockSum(v,red,4)*(1.f/FDIM);
  float dv = v-m;
  float var = blockSum(dv*dv,red,4)*(1.f/FDIM);
  float hn = dv*rsqrtf(var+1e-5f)*lg[t]+lb[t];
  sh[t]=hn;
  __syncthreads();
  if(t<HID){
    float a=b1[t];
    #pragma unroll 8
    for(int k=0;k<FDIM;k++) a += sh[k]*w1[k*HID+t];
    hidsh[t]=siluf(a);
  }
  __syncthreads();
  if(t<DDIM){
    float a=b2[t];
    #pragma unroll 8
    for(int k=0;k<HID;k++) a += hidsh[k]*w2[k*DDIM+t];
    pre[t]=a;
  }
  __syncthreads();
  if(t<DDIM){
    float vv=pre[t];
    float s=vv;
    #pragma unroll
    for(int o=8;o;o>>=1) s+=__shfl_xor_sync(0xffffu,s,o);
    float mm=s*(1.f/DDIM);
    float d=vv-mm; float q=d*d;
    #pragma unroll
    for(int o=8;o;o>>=1) q+=__shfl_xor_sync(0xffffu,q,o);
    float vr=q*(1.f/DDIM);
    g_src[atom*DDIM+t]=d*rsqrtf(vr+1e-5f)*sg[t]+sb[t];
  }
}

// ---------------- kernel 2: per-graph source mean ----------------
__global__ void mean_kernel(){
  int g=blockIdx.x, t=threadIdx.x;
  float acc[DDIM];
  #pragma unroll
  for(int c=0;c<DDIM;c++) acc[c]=0.f;
  for(int a=t;a<NATOM;a+=256){
    const float* p=&g_src[(g*NATOM+a)*DDIM];
    #pragma unroll
    for(int c=0;c<DDIM;c++) acc[c]+=p[c];
  }
  __shared__ float red[DDIM];
  if(t<DDIM) red[t]=0.f;
  __syncthreads();
  #pragma unroll
  for(int c=0;c<DDIM;c++){
    float s=acc[c];
    #pragma unroll
    for(int o=16;o;o>>=1) s+=__shfl_xor_sync(0xffffffffu,s,o);
    if((t&31)==0) atomicAdd(&red[c],s);
  }
  __syncthreads();
  if(t<DDIM) g_mean[g*DDIM+t]=red[t]*(1.f/NATOM);
}

// ---------------- kernel 3: pair loop + shell statistics ----------------
__global__ void __launch_bounds__(256,1)
pair_kernel(const float* __restrict__ pos,
            const float* __restrict__ kw1g, const float* __restrict__ kb1g,
            const float* __restrict__ kw2g, const float* __restrict__ kb2g,
            const float* __restrict__ kscr)
{
  extern __shared__ float smem[];
  float* px   = smem;                 // 512
  float* py   = px+NATOM;             // 512
  float* pz   = py+NATOM;             // 512
  float* ssrc = pz+NATOM;             // 512*16
  float* kers = ssrc+NATOM*DDIM;      // 8*512
  float* kw1  = kers+APB*NATOM;       // 320
  float* kb1  = kw1+320;              // 32
  float* kw2  = kb1+32;               // 32
  unsigned char* shl = (unsigned char*)(kw2+32); // 8*512 bytes

  int t=threadIdx.x;
  int blk=blockIdx.x;
  int g = blk/(NATOM/APB);
  int ibase = (blk%(NATOM/APB))*APB;

  for(int a=t;a<NATOM;a+=256){
    int ga=g*NATOM+a;
    px[a]=pos[ga*3+0]; py[a]=pos[ga*3+1]; pz[a]=pos[ga*3+2];
  }
  for(int idx=t; idx<NATOM*DDIM; idx+=256){
    int a=idx>>4, c=idx&15;
    ssrc[idx]=g_src[(g*NATOM+a)*DDIM+c]-g_mean[g*DDIM+c];
  }
  for(int k=t;k<320;k+=256) kw1[k]=kw1g[k];
  if(t<32) kb1[t]=kb1g[t];
  else if(t<64) kw2[t-32]=kw2g[t-32];
  __syncthreads();

  float kb2 = kb2g[0];
  float ks  = kscr[0];
  float screening = (ks>20.f)? ks : log1pf(__expf(ks));

  int w=t>>5, lane=t&31;
  int il=ibase+w;
  float xi=px[il], yi=py[il], zi=pz[il];
  float cnt[5]={0,0,0,0,0}, sr[5]={0,0,0,0,0}, sr2[5]={0,0,0,0,0};
  float* kerw=kers+w*NATOM;
  unsigned char* shw=shl+w*NATOM;

  // pass 1: per-pair kernel value + shell id
  for(int j=lane;j<NATOM;j+=32){
    float dx=xi-px[j], dy=yi-py[j], dz=zi-pz[j];
    float d2=dx*dx+dy*dy+dz*dz+1e-12f;
    float d=__fsqrt_rn(d2);
    bool valid = (j!=il) && (d>=5.0f);
    float kerv=0.f;
    int sidx=5;
    if(valid){
      sidx = (d<10.f)?0:((d<20.f)?1:((d<40.f)?2:((d<80.f)?3:4)));
      #pragma unroll
      for(int s=0;s<5;s++){
        if(sidx==s){ cnt[s]+=1.f; sr[s]+=d; sr2[s]+=d2; }
      }
      float base = __fdividef(__expf(-screening*d), d);
      float gin[10];
      gin[0]=d*0.2f; gin[1]=d*0.025f;
      #pragma unroll
      for(int k=0;k<8;k++){ float u=d-(5.f+5.f*(float)k); gin[2+k]=__expf(-0.04f*u*u); }
      float acc[32];
      #pragma unroll
      for(int h=0;h<32;h++) acc[h]=kb1[h];
      #pragma unroll
      for(int f=0;f<10;f++){
        float gf=gin[f];
        #pragma unroll
        for(int h=0;h<32;h++) acc[h]+=gf*kw1[f*32+h];
      }
      float outv=kb2;
      #pragma unroll
      for(int h=0;h<32;h++) outv += siluf(acc[h])*kw2[h];
      float gate=1.f+tanhf(outv);
      kerv=base*gate;
    }
    kerw[j]=kerv;
    shw[j]=(unsigned char)sidx;
  }
  __syncwarp();

  // pass 2: channel-parallel weighted accumulation (half-warps take even/odd j)
  float ws[5]={0,0,0,0,0};
  int ch = lane&15;
  for(int j=(lane>>4); j<NATOM; j+=2){
    float kv=kerw[j];
    int s=(int)shw[j];
    float p=kv*ssrc[j*DDIM+ch];
    #pragma unroll
    for(int q=0;q<5;q++) ws[q] += (s==q)? p : 0.f;
  }
  #pragma unroll
  for(int q=0;q<5;q++) ws[q]+=__shfl_xor_sync(0xffffffffu,ws[q],16);

  // reduce scalar stats across warp
  #pragma unroll
  for(int q=0;q<5;q++){
    #pragma unroll
    for(int o=16;o;o>>=1){
      cnt[q]+=__shfl_xor_sync(0xffffffffu,cnt[q],o);
      sr [q]+=__shfl_xor_sync(0xffffffffu,sr [q],o);
      sr2[q]+=__shfl_xor_sync(0xffffffffu,sr2[q],o);
    }
  }

  int ig=g*NATOM+il;
  float* outp=&g_shell[ig*SEIN];
  #pragma unroll
  for(int q=0;q<5;q++){
    float c=cnt[q];
    float den=fmaxf(c,1.f);
    if(lane<16)       outp[q*19+lane]=ws[q]/den;
    else if(lane==16) outp[q*19+16]=c;
    else if(lane==17) outp[q*19+17]=sr[q]/den;
    else if(lane==18) outp[q*19+18]=__fsqrt_rn(sr2[q]/den + 1e-12f);
  }
}

// ---------------- kernel 4: zero output ----------------
__global__ void zero_kernel(float* out,int nn){
  int t=threadIdx.x+blockIdx.x*blockDim.x;
  if(t<nn) out[t]=0.f;
}

// ---------------- kernel 5: shell embed + energy head + segment sum ----------------
__global__ void final_kernel(const int* __restrict__ batch,
  const float* __restrict__ selng, const float* __restrict__ selnb,
  const float* __restrict__ sew1,  const float* __restrict__ seb1,
  const float* __restrict__ sew2,  const float* __restrict__ seb2,
  const float* __restrict__ ehlng, const float* __restrict__ ehlnb,
  const float* __restrict__ ehw1,  const float* __restrict__ ehb1,
  const float* __restrict__ ehw2,  const float* __restrict__ ehb2,
  const float* __restrict__ fg, const float* __restrict__ es, float* out)
{
  __shared__ float red[8];
  __shared__ float shn[SEIN];
  __shared__ float hid[HID];
  __shared__ float ein[EHIN];
  __shared__ float en[EHIN];
  __shared__ float h2[HID];
  int atom=blockIdx.x, t=threadIdx.x;
  int g=batch[atom];
  const float* sp=&g_shell[atom*SEIN];
  float sv=(t<SEIN)?sp[t]:0.f;
  float mean=blockSum(sv,red,5)*(1.f/SEIN);
  float dv=(t<SEIN)?(sv-mean):0.f;
  float var=blockSum(dv*dv,red,5)*(1.f/SEIN);
  if(t<SEIN) shn[t]=dv*rsqrtf(var+1e-5f)*selng[t]+selnb[t];
  __syncthreads();
  if(t<HID){
    float a=seb1[t];
    #pragma unroll 5
    for(int k=0;k<SEIN;k++) a+=shn[k]*sew1[k*HID+t];
    hid[t]=siluf(a);
  }
  __syncthreads();
  if(t<DDIM){
    float a=seb2[t];
    #pragma unroll 8
    for(int k=0;k<HID;k++) a+=hid[k]*sew2[k*DDIM+t];
    float sc=g_src[atom*DDIM+t]-g_mean[g*DDIM+t];
    ein[t]=sc; ein[16+t]=a; ein[32+t]=sc*a; ein[48+t]=sc-a;
  }
  if(t<SEIN) ein[64+t]=sv;
  __syncthreads();
  float ev=(t<EHIN)?ein[t]:0.f;
  float em=blockSum(ev,red,5)*(1.f/EHIN);
  float edv=(t<EHIN)?(ev-em):0.f;
  float evar=blockSum(edv*edv,red,5)*(1.f/EHIN);
  if(t<EHIN) en[t]=edv*rsqrtf(evar+1e-5f)*ehlng[t]+ehlnb[t];
  __syncthreads();
  if(t<HID){
    float a=ehb1[t];
    #pragma unroll 3
    for(int k=0;k<EHIN;k++) a+=en[k]*ehw1[k*HID+t];
    h2[t]=siluf(a);
  }
  __syncthreads();
  if(t<32){
    float p=h2[t]*ehw2[t]+h2[t+32]*ehw2[t+32];
    #pragma unroll
    for(int o=16;o;o>>=1) p+=__shfl_xor_sync(0xffffffffu,p,o);
    if(t==0){
      float pa=p+ehb2[0];
      pa *= tanhf(fg[0])*__expf(es[0]);
      atomicAdd(&out[g],pa);
    }
  }
}

extern "C" void kernel_launch(void* const* d_in, const int* in_sizes, int n_in,
                              void* d_out, int out_size) {
  const float* x   = (const float*)d_in[0];
  const float* pos = (const float*)d_in[1];
  const int* batch = (const int*)d_in[2];
  // 'num_graphs' may or may not be materialized as an input; detect.
  int off = (in_sizes[3]==1) ? 4 : 3;
  const float* in_ln_g = (const float*)d_in[off+0];
  const float* in_ln_b = (const float*)d_in[off+1];
  const float* src_w1  = (const float*)d_in[off+2];
  const float* src_b1  = (const float*)d_in[off+3];
  const float* src_w2  = (const float*)d_in[off+4];
  const float* src_b2  = (const float*)d_in[off+5];
  const float* src_ln_g= (const float*)d_in[off+6];
  const float* src_ln_b= (const float*)d_in[off+7];
  const float* se_ln_g = (const float*)d_in[off+8];
  const float* se_ln_b = (const float*)d_in[off+9];
  const float* se_w1   = (const float*)d_in[off+10];
  const float* se_b1   = (const float*)d_in[off+11];
  const float* se_w2   = (const float*)d_in[off+12];
  const float* se_b2   = (const float*)d_in[off+13];
  const float* eh_ln_g = (const float*)d_in[off+14];
  const float* eh_ln_b = (const float*)d_in[off+15];
  const float* eh_w1   = (const float*)d_in[off+16];
  const float* eh_b1   = (const float*)d_in[off+17];
  const float* eh_w2   = (const float*)d_in[off+18];
  const float* eh_b2   = (const float*)d_in[off+19];
  const float* k_screen= (const float*)d_in[off+20];
  const float* kg_w1   = (const float*)d_in[off+21];
  const float* kg_b1   = (const float*)d_in[off+22];
  const float* kg_w2   = (const float*)d_in[off+23];
  const float* kg_b2   = (const float*)d_in[off+24];
  const float* far_gate= (const float*)d_in[off+25];
  const float* en_scale= (const float*)d_in[off+26];
  float* out = (float*)d_out;

  const int smem_bytes = (3*NATOM + NATOM*DDIM + APB*NATOM + 320 + 32 + 32)*4 + APB*NATOM;
  cudaFuncSetAttribute(pair_kernel, cudaFuncAttributeMaxDynamicSharedMemorySize, smem_bytes);

  src_kernel<<<MTOT,FDIM>>>(x, in_ln_g, in_ln_b, src_w1, src_b1, src_w2, src_b2,
                            src_ln_g, src_ln_b);
  mean_kernel<<<BGR,256>>>();
  pair_kernel<<<NBLK,256,smem_bytes>>>(pos, kg_w1, kg_b1, kg_w2, kg_b2, k_screen);
  zero_kernel<<<1,32>>>(out, out_size);
  final_kernel<<<MTOT,160>>>(batch, se_ln_g, se_ln_b, se_w1, se_b1, se_w2, se_b2,
                             eh_ln_g, eh_ln_b, eh_w1, eh_b1, eh_w2, eh_b2,
                             far_gate, en_scale, out);
}

// round 6
// speedup vs baseline: 2.0997x; 2.0997x over previous
#include <cuda_runtime.h>
#include <cuda_bf16.h>
#include <math.h>

#define MTOT 8192
#define BGR  16
#define NATOM 512
#define FDIM 128
#define HID  64
#define DDIM 16
#define SEIN 95
#define EHIN 159
#define APB  8          // atoms per block in pair kernel
#define NBLK (MTOT/APB) // 1024
#define TABN 16384
#define TAB_LO 5.0f
#define TAB_HI 141.0f

__device__ float g_src[MTOT*DDIM];
__device__ float g_mean[BGR*DDIM];
__device__ float g_shell[MTOT*SEIN];
__device__ float g_ktab[TABN];

__device__ __forceinline__ float siluf(float x){ return x * (1.f/(1.f + __expf(-x))); }

__device__ __forceinline__ float blockSum(float v, float* red, int nw){
  #pragma unroll
  for (int o=16;o>0;o>>=1) v += __shfl_xor_sync(0xffffffffu, v, o);
  if ((threadIdx.x&31)==0) red[threadIdx.x>>5]=v;
  __syncthreads();
  float s=0.f;
  for(int k=0;k<nw;k++) s += red[k];
  __syncthreads();
  return s;
}

// ---------------- kernel 0: kernel-value lookup table ----------------
// ker(d) = exp(-softplus(ks)*d)/d * (1 + tanh(silu(gin@w1+b1)@w2+b2))
__global__ void ktab_kernel(const float* __restrict__ kw1, const float* __restrict__ kb1,
                            const float* __restrict__ kw2, const float* __restrict__ kb2,
                            const float* __restrict__ kscr)
{
  int i = blockIdx.x*blockDim.x + threadIdx.x;
  if(i>=TABN) return;
  float d = TAB_LO + (float)i * ((TAB_HI-TAB_LO)/(float)(TABN-1));
  float ks = kscr[0];
  float screening = (ks>20.f)? ks : log1pf(expf(ks));
  float base = expf(-screening*d)/d;
  float gin[10];
  gin[0]=d*0.2f; gin[1]=d*0.025f;
  #pragma unroll
  for(int k=0;k<8;k++){ float u=d-(5.f+5.f*(float)k); gin[2+k]=expf(-0.04f*u*u); }
  float outv = kb2[0];
  for(int h=0;h<32;h++){
    float a = kb1[h];
    #pragma unroll
    for(int f=0;f<10;f++) a += gin[f]*kw1[f*32+h];
    outv += (a*(1.f/(1.f+expf(-a)))) * kw2[h];
  }
  g_ktab[i] = base * (1.f + tanhf(outv));
}

// ---------------- kernel 1: per-atom source features (+ zero out) ----------------
__global__ void src_kernel(const float* __restrict__ x,
                           const float* __restrict__ lg, const float* __restrict__ lb,
                           const float* __restrict__ w1, const float* __restrict__ b1,
                           const float* __restrict__ w2, const float* __restrict__ b2,
                           const float* __restrict__ sg, const float* __restrict__ sb,
                           float* __restrict__ out, int out_n)
{
  __shared__ float sh[FDIM];
  __shared__ float red[4];
  __shared__ float hidsh[HID];
  __shared__ float pre[DDIM];
  int atom=blockIdx.x, t=threadIdx.x;
  if(atom==0 && t<out_n) out[t]=0.f;
  float v = x[atom*FDIM+t];
  float m = blockSum(v,red,4)*(1.f/FDIM);
  float dv = v-m;
  float var = blockSum(dv*dv,red,4)*(1.f/FDIM);
  float hn = dv*rsqrtf(var+1e-5f)*lg[t]+lb[t];
  sh[t]=hn;
  __syncthreads();
  if(t<HID){
    float a=b1[t];
    #pragma unroll 8
    for(int k=0;k<FDIM;k++) a += sh[k]*w1[k*HID+t];
    hidsh[t]=siluf(a);
  }
  __syncthreads();
  if(t<DDIM){
    float a=b2[t];
    #pragma unroll 8
    for(int k=0;k<HID;k++) a += hidsh[k]*w2[k*DDIM+t];
    pre[t]=a;
  }
  __syncthreads();
  if(t<DDIM){
    float vv=pre[t];
    float s=vv;
    #pragma unroll
    for(int o=8;o;o>>=1) s+=__shfl_xor_sync(0xffffu,s,o);
    float mm=s*(1.f/DDIM);
    float d=vv-mm; float q=d*d;
    #pragma unroll
    for(int o=8;o;o>>=1) q+=__shfl_xor_sync(0xffffu,q,o);
    float vr=q*(1.f/DDIM);
    g_src[atom*DDIM+t]=d*rsqrtf(vr+1e-5f)*sg[t]+sb[t];
  }
}

// ---------------- kernel 2: per-graph source mean ----------------
__global__ void mean_kernel(){
  int g=blockIdx.x, t=threadIdx.x;
  float acc[DDIM];
  #pragma unroll
  for(int c=0;c<DDIM;c++) acc[c]=0.f;
  for(int a=t;a<NATOM;a+=256){
    const float* p=&g_src[(g*NATOM+a)*DDIM];
    #pragma unroll
    for(int c=0;c<DDIM;c++) acc[c]+=p[c];
  }
  __shared__ float red[DDIM];
  if(t<DDIM) red[t]=0.f;
  __syncthreads();
  #pragma unroll
  for(int c=0;c<DDIM;c++){
    float s=acc[c];
    #pragma unroll
    for(int o=16;o;o>>=1) s+=__shfl_xor_sync(0xffffffffu,s,o);
    if((t&31)==0) atomicAdd(&red[c],s);
  }
  __syncthreads();
  if(t<DDIM) g_mean[g*DDIM+t]=red[t]*(1.f/NATOM);
}

// ---------------- kernel 3: pair loop + shell statistics ----------------
__global__ void __launch_bounds__(256)
pair_kernel(const float* __restrict__ pos)
{
  extern __shared__ float smem[];
  float* px   = smem;                 // 512
  float* py   = px+NATOM;             // 512
  float* pz   = py+NATOM;             // 512
  float* ssrc = pz+NATOM;             // 512*16
  float* kers = ssrc+NATOM*DDIM;      // 8*512
  unsigned char* shl = (unsigned char*)(kers+APB*NATOM); // 8*512 bytes

  int t=threadIdx.x;
  int blk=blockIdx.x;
  int g = blk/(NATOM/APB);
  int ibase = (blk%(NATOM/APB))*APB;

  for(int a=t;a<NATOM;a+=256){
    int ga=g*NATOM+a;
    px[a]=pos[ga*3+0]; py[a]=pos[ga*3+1]; pz[a]=pos[ga*3+2];
  }
  for(int idx=t; idx<NATOM*DDIM; idx+=256){
    int a=idx>>4, c=idx&15;
    ssrc[idx]=g_src[(g*NATOM+a)*DDIM+c]-g_mean[g*DDIM+c];
  }
  __syncthreads();

  int w=t>>5, lane=t&31;
  int il=ibase+w;
  float xi=px[il], yi=py[il], zi=pz[il];
  float cnt[5]={0,0,0,0,0}, sr[5]={0,0,0,0,0}, sr2[5]={0,0,0,0,0};
  float* kerw=kers+w*NATOM;
  unsigned char* shw=shl+w*NATOM;

  const float tscale = (float)(TABN-1)/(TAB_HI-TAB_LO);

  // pass 1: per-pair kernel value (table lerp) + shell id + scalar stats
  for(int j=lane;j<NATOM;j+=32){
    float dx=xi-px[j], dy=yi-py[j], dz=zi-pz[j];
    float d2=dx*dx+dy*dy+dz*dz+1e-12f;
    float d=__fsqrt_rn(d2);
    bool valid = (j!=il) && (d>=5.0f);
    float kerv=0.f;
    int sidx=5;
    if(valid){
      sidx = (d<10.f)?0:((d<20.f)?1:((d<40.f)?2:((d<80.f)?3:4)));
      #pragma unroll
      for(int s=0;s<5;s++){
        if(sidx==s){ cnt[s]+=1.f; sr[s]+=d; sr2[s]+=d2; }
      }
      float u=(d-TAB_LO)*tscale;
      u=fminf(u,(float)(TABN-1)-1e-3f);
      int i0=(int)u; float fr=u-(float)i0;
      float t0=__ldg(&g_ktab[i0]), t1=__ldg(&g_ktab[i0+1]);
      kerv=fmaf(fr,t1-t0,t0);
    }
    kerw[j]=kerv;
    shw[j]=(unsigned char)sidx;
  }
  __syncwarp();

  // pass 2: channel-parallel weighted accumulation (half-warps take even/odd j)
  float ws[5]={0,0,0,0,0};
  int ch = lane&15;
  #pragma unroll 2
  for(int j=(lane>>4); j<NATOM; j+=2){
    float kv=kerw[j];
    int s=(int)shw[j];
    float p=kv*ssrc[j*DDIM+ch];
    #pragma unroll
    for(int q=0;q<5;q++) ws[q] += (s==q)? p : 0.f;
  }
  #pragma unroll
  for(int q=0;q<5;q++) ws[q]+=__shfl_xor_sync(0xffffffffu,ws[q],16);

  #pragma unroll
  for(int q=0;q<5;q++){
    #pragma unroll
    for(int o=16;o;o>>=1){
      cnt[q]+=__shfl_xor_sync(0xffffffffu,cnt[q],o);
      sr [q]+=__shfl_xor_sync(0xffffffffu,sr [q],o);
      sr2[q]+=__shfl_xor_sync(0xffffffffu,sr2[q],o);
    }
  }

  int ig=g*NATOM+il;
  float* outp=&g_shell[ig*SEIN];
  #pragma unroll
  for(int q=0;q<5;q++){
    float c=cnt[q];
    float den=fmaxf(c,1.f);
    if(lane<16)       outp[q*19+lane]=ws[q]/den;
    else if(lane==16) outp[q*19+16]=c;
    else if(lane==17) outp[q*19+17]=sr[q]/den;
    else if(lane==18) outp[q*19+18]=__fsqrt_rn(sr2[q]/den + 1e-12f);
  }
}

// ---------------- kernel 5: shell embed + energy head + segment sum ----------------
__global__ void final_kernel(const int* __restrict__ batch,
  const float* __restrict__ selng, const float* __restrict__ selnb,
  const float* __restrict__ sew1,  const float* __restrict__ seb1,
  const float* __restrict__ sew2,  const float* __restrict__ seb2,
  const float* __restrict__ ehlng, const float* __restrict__ ehlnb,
  const float* __restrict__ ehw1,  const float* __restrict__ ehb1,
  const float* __restrict__ ehw2,  const float* __restrict__ ehb2,
  const float* __restrict__ fg, const float* __restrict__ es, float* out)
{
  __shared__ float red[8];
  __shared__ float shn[SEIN];
  __shared__ float hid[HID];
  __shared__ float ein[EHIN];
  __shared__ float en[EHIN];
  __shared__ float h2[HID];
  int atom=blockIdx.x, t=threadIdx.x;
  int g=batch[atom];
  const float* sp=&g_shell[atom*SEIN];
  float sv=(t<SEIN)?sp[t]:0.f;
  float mean=blockSum(sv,red,5)*(1.f/SEIN);
  float dv=(t<SEIN)?(sv-mean):0.f;
  float var=blockSum(dv*dv,red,5)*(1.f/SEIN);
  if(t<SEIN) shn[t]=dv*rsqrtf(var+1e-5f)*selng[t]+selnb[t];
  __syncthreads();
  if(t<HID){
    float a=seb1[t];
    #pragma unroll 5
    for(int k=0;k<SEIN;k++) a+=shn[k]*sew1[k*HID+t];
    hid[t]=siluf(a);
  }
  __syncthreads();
  if(t<DDIM){
    float a=seb2[t];
    #pragma unroll 8
    for(int k=0;k<HID;k++) a+=hid[k]*sew2[k*DDIM+t];
    float sc=g_src[atom*DDIM+t]-g_mean[g*DDIM+t];
    ein[t]=sc; ein[16+t]=a; ein[32+t]=sc*a; ein[48+t]=sc-a;
  }
  if(t<SEIN) ein[64+t]=sv;
  __syncthreads();
  float ev=(t<EHIN)?ein[t]:0.f;
  float em=blockSum(ev,red,5)*(1.f/EHIN);
  float edv=(t<EHIN)?(ev-em):0.f;
  float evar=blockSum(edv*edv,red,5)*(1.f/EHIN);
  if(t<EHIN) en[t]=edv*rsqrtf(evar+1e-5f)*ehlng[t]+ehlnb[t];
  __syncthreads();
  if(t<HID){
    float a=ehb1[t];
    #pragma unroll 3
    for(int k=0;k<EHIN;k++) a+=en[k]*ehw1[k*HID+t];
    h2[t]=siluf(a);
  }
  __syncthreads();
  if(t<32){
    float p=h2[t]*ehw2[t]+h2[t+32]*ehw2[t+32];
    #pragma unroll
    for(int o=16;o;o>>=1) p+=__shfl_xor_sync(0xffffffffu,p,o);
    if(t==0){
      float pa=p+ehb2[0];
      pa *= tanhf(fg[0])*__expf(es[0]);
      atomicAdd(&out[g],pa);
    }
  }
}

extern "C" void kernel_launch(void* const* d_in, const int* in_sizes, int n_in,
                              void* d_out, int out_size) {
  const float* x   = (const float*)d_in[0];
  const float* pos = (const float*)d_in[1];
  const int* batch = (const int*)d_in[2];
  int off = (in_sizes[3]==1) ? 4 : 3;
  const float* in_ln_g = (const float*)d_in[off+0];
  const float* in_ln_b = (const float*)d_in[off+1];
  const float* src_w1  = (const float*)d_in[off+2];
  const float* src_b1  = (const float*)d_in[off+3];
  const float* src_w2  = (const float*)d_in[off+4];
  const float* src_b2  = (const float*)d_in[off+5];
  const float* src_ln_g= (const float*)d_in[off+6];
  const float* src_ln_b= (const float*)d_in[off+7];
  const float* se_ln_g = (const float*)d_in[off+8];
  const float* se_ln_b = (const float*)d_in[off+9];
  const float* se_w1   = (const float*)d_in[off+10];
  const float* se_b1   = (const float*)d_in[off+11];
  const float* se_w2   = (const float*)d_in[off+12];
  const float* se_b2   = (const float*)d_in[off+13];
  const float* eh_ln_g = (const float*)d_in[off+14];
  const float* eh_ln_b = (const float*)d_in[off+15];
  const float* eh_w1   = (const float*)d_in[off+16];
  const float* eh_b1   = (const float*)d_in[off+17];
  const float* eh_w2   = (const float*)d_in[off+18];
  const float* eh_b2   = (const float*)d_in[off+19];
  const float* k_screen= (const float*)d_in[off+20];
  const float* kg_w1   = (const float*)d_in[off+21];
  const float* kg_b1   = (const float*)d_in[off+22];
  const float* kg_w2   = (const float*)d_in[off+23];
  const float* kg_b2   = (const float*)d_in[off+24];
  const float* far_gate= (const float*)d_in[off+25];
  const float* en_scale= (const float*)d_in[off+26];
  float* out = (float*)d_out;

  const int smem_bytes = (3*NATOM + NATOM*DDIM + APB*NATOM)*4 + APB*NATOM;
  cudaFuncSetAttribute(pair_kernel, cudaFuncAttributeMaxDynamicSharedMemorySize, smem_bytes);

  ktab_kernel<<<TABN/256,256>>>(kg_w1, kg_b1, kg_w2, kg_b2, k_screen);
  src_kernel<<<MTOT,FDIM>>>(x, in_ln_g, in_ln_b, src_w1, src_b1, src_w2, src_b2,
                            src_ln_g, src_ln_b, out, out_size);
  mean_kernel<<<BGR,256>>>();
  pair_kernel<<<NBLK,256,smem_bytes>>>(pos);
  final_kernel<<<MTOT,160>>>(batch, se_ln_g, se_ln_b, se_w1, se_b1, se_w2, se_b2,
                             eh_ln_g, eh_ln_b, eh_w1, eh_b1, eh_w2, eh_b2,
                             far_gate, en_scale, out);
}